// round 2
// baseline (speedup 1.0000x reference)
#include <cuda_runtime.h>
#include <math.h>

// Problem constants
#define DMODEL 1024
#define NBATCH 8
#define SEQ    2048
#define NTOK   (NBATCH * SEQ)   // 16384

// Scratch for Q, K, V (sanctioned __device__ globals; 3 x 64 MB)
__device__ float g_Q[NTOK * DMODEL];
__device__ float g_K[NTOK * DMODEL];
__device__ float g_V[NTOK * DMODEL];

// ---------------------------------------------------------------------------
// Kernel 1: fused QKV projection.  out = X @ W + b
// X: [16384, 1024], W: [1024, 1024] (k-major rows), b: [1024]
// 128x128 block tile, BK=8, 256 threads, 8x8 per-thread microtile.
// grid = (N/128, M/128, 3); z selects (Wq,bq)->g_Q etc.
// ---------------------------------------------------------------------------
__global__ __launch_bounds__(256) void qkv_kernel(
    const float* __restrict__ X,
    const float* __restrict__ Wq, const float* __restrict__ bq,
    const float* __restrict__ Wk, const float* __restrict__ bk,
    const float* __restrict__ Wv, const float* __restrict__ bv)
{
    __shared__ float As[8][128];   // As[k][m]
    __shared__ float Bs[8][128];   // Bs[k][n]

    const float* W; const float* bias; float* out;
    if (blockIdx.z == 0)      { W = Wq; bias = bq; out = g_Q; }
    else if (blockIdx.z == 1) { W = Wk; bias = bk; out = g_K; }
    else                      { W = Wv; bias = bv; out = g_V; }

    const int m0 = blockIdx.y * 128;
    const int n0 = blockIdx.x * 128;
    const int tid = threadIdx.x;
    const int tx = tid & 15;        // 0..15 -> output cols tx*8..
    const int ty = tid >> 4;        // 0..15 -> output rows ty*8..

    // load mappings
    const int arow = tid >> 1;          // 0..127 (m)
    const int ac4  = (tid & 1) * 4;     // k sub-offset
    const int brow = tid >> 5;          // 0..7   (k)
    const int bc4  = (tid & 31) * 4;    // n sub-offset

    float acc[8][8];
    #pragma unroll
    for (int i = 0; i < 8; i++)
        #pragma unroll
        for (int j = 0; j < 8; j++) acc[i][j] = 0.f;

    // prefetch first tile
    float4 av  = *(const float4*)&X[(size_t)(m0 + arow) * DMODEL + ac4];
    float4 bv4 = *(const float4*)&W[(size_t)brow * DMODEL + n0 + bc4];

    for (int k0 = 0; k0 < DMODEL; k0 += 8) {
        As[ac4 + 0][arow] = av.x;
        As[ac4 + 1][arow] = av.y;
        As[ac4 + 2][arow] = av.z;
        As[ac4 + 3][arow] = av.w;
        *(float4*)&Bs[brow][bc4] = bv4;
        __syncthreads();

        if (k0 + 8 < DMODEL) {
            av  = *(const float4*)&X[(size_t)(m0 + arow) * DMODEL + (k0 + 8) + ac4];
            bv4 = *(const float4*)&W[(size_t)(k0 + 8 + brow) * DMODEL + n0 + bc4];
        }

        #pragma unroll
        for (int k = 0; k < 8; k++) {
            float a[8], b[8];
            #pragma unroll
            for (int i = 0; i < 8; i++) a[i] = As[k][ty * 8 + i];
            #pragma unroll
            for (int j = 0; j < 8; j++) b[j] = Bs[k][tx * 8 + j];
            #pragma unroll
            for (int i = 0; i < 8; i++)
                #pragma unroll
                for (int j = 0; j < 8; j++)
                    acc[i][j] = fmaf(a[i], b[j], acc[i][j]);
        }
        __syncthreads();
    }

    // bias + store
    float bb[8];
    #pragma unroll
    for (int j = 0; j < 8; j++) bb[j] = bias[n0 + tx * 8 + j];
    #pragma unroll
    for (int i = 0; i < 8; i++) {
        const size_t gr = (size_t)(m0 + ty * 8 + i) * DMODEL + n0 + tx * 8;
        float4 s0 = make_float4(acc[i][0] + bb[0], acc[i][1] + bb[1],
                                acc[i][2] + bb[2], acc[i][3] + bb[3]);
        float4 s1 = make_float4(acc[i][4] + bb[4], acc[i][5] + bb[5],
                                acc[i][6] + bb[6], acc[i][7] + bb[7]);
        *(float4*)&out[gr]     = s0;
        *(float4*)&out[gr + 4] = s1;
    }
}

// ---------------------------------------------------------------------------
// Kernel 2: flash-style attention with online softmax.
// One CTA per (batch, 128-query tile): 128 CTAs, 256 threads.
// Scores S = Q Kt (128x128, K-dim 1024) per key tile; online softmax;
// O accumulated unnormalized directly in d_out (L2-resident), rescaled by
// alpha per key tile, normalized by 1/l on the last tile.
// ---------------------------------------------------------------------------
struct AttnSmem {
    float Ps[128][129];   // P transposed: Ps[key][query]
    float Qs[8][128];     // Qs[d][query]
    float Ks[8][128];     // Ks[d][key]  (reused as Vs[k][n] in O phase)
    float m_s[128];
    float l_s[128];
    float alpha_s[128];
};

__global__ __launch_bounds__(256) void attn_kernel(float* __restrict__ Out)
{
    extern __shared__ char smem_bytes[];
    AttnSmem& sm = *reinterpret_cast<AttnSmem*>(smem_bytes);

    const int tid = threadIdx.x;
    const int tx = tid & 15;
    const int ty = tid >> 4;
    const int b  = blockIdx.y;
    const int qt = blockIdx.x;
    const int q0    = b * SEQ + qt * 128;   // global query token row
    const int kbase = b * SEQ;

    if (tid < 128) {
        sm.m_s[tid] = __int_as_float(0xff800000);  // -inf
        sm.l_s[tid] = 0.f;
    }
    __syncthreads();

    const int arow = tid >> 1;         // 0..127
    const int ac4  = (tid & 1) * 4;
    const int vrow = tid >> 5;         // 0..7
    const int vc4  = (tid & 31) * 4;

    for (int kt = 0; kt < 16; kt++) {
        const int k0 = kbase + kt * 128;

        // ---------------- scores: S = Q @ K^T ----------------
        float acc[8][8];
        #pragma unroll
        for (int i = 0; i < 8; i++)
            #pragma unroll
            for (int j = 0; j < 8; j++) acc[i][j] = 0.f;

        float4 qv = *(const float4*)&g_Q[(size_t)(q0 + arow) * DMODEL + ac4];
        float4 kv = *(const float4*)&g_K[(size_t)(k0 + arow) * DMODEL + ac4];

        for (int dk = 0; dk < DMODEL; dk += 8) {
            sm.Qs[ac4 + 0][arow] = qv.x;
            sm.Qs[ac4 + 1][arow] = qv.y;
            sm.Qs[ac4 + 2][arow] = qv.z;
            sm.Qs[ac4 + 3][arow] = qv.w;
            sm.Ks[ac4 + 0][arow] = kv.x;
            sm.Ks[ac4 + 1][arow] = kv.y;
            sm.Ks[ac4 + 2][arow] = kv.z;
            sm.Ks[ac4 + 3][arow] = kv.w;
            __syncthreads();

            if (dk + 8 < DMODEL) {
                qv = *(const float4*)&g_Q[(size_t)(q0 + arow) * DMODEL + dk + 8 + ac4];
                kv = *(const float4*)&g_K[(size_t)(k0 + arow) * DMODEL + dk + 8 + ac4];
            }

            #pragma unroll
            for (int k = 0; k < 8; k++) {
                float a[8], bb[8];
                #pragma unroll
                for (int i = 0; i < 8; i++) a[i] = sm.Qs[k][ty * 8 + i];
                #pragma unroll
                for (int j = 0; j < 8; j++) bb[j] = sm.Ks[k][tx * 8 + j];
                #pragma unroll
                for (int i = 0; i < 8; i++)
                    #pragma unroll
                    for (int j = 0; j < 8; j++)
                        acc[i][j] = fmaf(a[i], bb[j], acc[i][j]);
            }
            __syncthreads();
        }

        // ---------------- online softmax ----------------
        #pragma unroll
        for (int i = 0; i < 8; i++) {
            const int row = ty * 8 + i;
            float lm = acc[i][0];
            #pragma unroll
            for (int j = 1; j < 8; j++) lm = fmaxf(lm, acc[i][j]);
            #pragma unroll
            for (int off = 8; off >= 1; off >>= 1)
                lm = fmaxf(lm, __shfl_xor_sync(0xffffffffu, lm, off, 16));

            const float m_old = sm.m_s[row];
            const float m_new = fmaxf(m_old, lm);
            float ps = 0.f;
            #pragma unroll
            for (int j = 0; j < 8; j++) {
                acc[i][j] = __expf(acc[i][j] - m_new);
                ps += acc[i][j];
            }
            #pragma unroll
            for (int off = 8; off >= 1; off >>= 1)
                ps += __shfl_xor_sync(0xffffffffu, ps, off, 16);

            const float alpha = __expf(m_old - m_new);
            if (tx == 0) {
                sm.m_s[row]     = m_new;
                sm.l_s[row]     = sm.l_s[row] * alpha + ps;
                sm.alpha_s[row] = alpha;
            }
        }

        // store P transposed: Ps[key][query]
        #pragma unroll
        for (int i = 0; i < 8; i++)
            #pragma unroll
            for (int j = 0; j < 8; j++)
                sm.Ps[tx * 8 + j][ty * 8 + i] = acc[i][j];
        __syncthreads();

        // ---------------- O update: O += P @ V (8 chunks of 128 cols) -----
        const bool first = (kt == 0);
        const bool last  = (kt == 15);

        for (int nc = 0; nc < 8; nc++) {
            const int n0 = nc * 128;
            float oacc[8][8];
            if (first) {
                #pragma unroll
                for (int i = 0; i < 8; i++)
                    #pragma unroll
                    for (int j = 0; j < 8; j++) oacc[i][j] = 0.f;
            } else {
                #pragma unroll
                for (int i = 0; i < 8; i++) {
                    const int row = ty * 8 + i;
                    const float al = sm.alpha_s[row];
                    const size_t gr = (size_t)(q0 + row) * DMODEL + n0 + tx * 8;
                    float4 p0 = *(const float4*)&Out[gr];
                    float4 p1 = *(const float4*)&Out[gr + 4];
                    oacc[i][0] = p0.x * al; oacc[i][1] = p0.y * al;
                    oacc[i][2] = p0.z * al; oacc[i][3] = p0.w * al;
                    oacc[i][4] = p1.x * al; oacc[i][5] = p1.y * al;
                    oacc[i][6] = p1.z * al; oacc[i][7] = p1.w * al;
                }
            }

            float4 vv = *(const float4*)&g_V[(size_t)(k0 + vrow) * DMODEL + n0 + vc4];
            for (int dk2 = 0; dk2 < 128; dk2 += 8) {
                *(float4*)&sm.Ks[vrow][vc4] = vv;   // reuse Ks as Vs[k][n]
                __syncthreads();
                if (dk2 + 8 < 128)
                    vv = *(const float4*)&g_V[(size_t)(k0 + dk2 + 8 + vrow) * DMODEL + n0 + vc4];

                #pragma unroll
                for (int k = 0; k < 8; k++) {
                    float a[8], bb[8];
                    #pragma unroll
                    for (int i = 0; i < 8; i++) a[i] = sm.Ps[dk2 + k][ty * 8 + i];
                    #pragma unroll
                    for (int j = 0; j < 8; j++) bb[j] = sm.Ks[k][tx * 8 + j];
                    #pragma unroll
                    for (int i = 0; i < 8; i++)
                        #pragma unroll
                        for (int j = 0; j < 8; j++)
                            oacc[i][j] = fmaf(a[i], bb[j], oacc[i][j]);
                }
                __syncthreads();
            }

            // store (normalize on last key tile)
            #pragma unroll
            for (int i = 0; i < 8; i++) {
                const int row = ty * 8 + i;
                const float sc = last ? (1.f / sm.l_s[row]) : 1.f;
                const size_t gr = (size_t)(q0 + row) * DMODEL + n0 + tx * 8;
                float4 s0 = make_float4(oacc[i][0] * sc, oacc[i][1] * sc,
                                        oacc[i][2] * sc, oacc[i][3] * sc);
                float4 s1 = make_float4(oacc[i][4] * sc, oacc[i][5] * sc,
                                        oacc[i][6] * sc, oacc[i][7] * sc);
                *(float4*)&Out[gr]     = s0;
                *(float4*)&Out[gr + 4] = s1;
            }
        }
        __syncthreads();  // protect smem reuse next key tile
    }
}

// ---------------------------------------------------------------------------
extern "C" void kernel_launch(void* const* d_in, const int* in_sizes, int n_in,
                              void* d_out, int out_size)
{
    const float* X  = (const float*)d_in[0];
    const float* Wq = (const float*)d_in[1];
    const float* bq = (const float*)d_in[2];
    const float* Wk = (const float*)d_in[3];
    const float* bk = (const float*)d_in[4];
    const float* Wv = (const float*)d_in[5];
    const float* bv = (const float*)d_in[6];
    float* Out = (float*)d_out;

    // QKV projections: grid (N/128, M/128, 3)
    dim3 g1(DMODEL / 128, NTOK / 128, 3);
    qkv_kernel<<<g1, 256>>>(X, Wq, bq, Wk, bk, Wv, bv);

    // Attention: one CTA per (q-tile, batch)
    cudaFuncSetAttribute(attn_kernel, cudaFuncAttributeMaxDynamicSharedMemorySize,
                         (int)sizeof(AttnSmem));
    attn_kernel<<<dim3(SEQ / 128, NBATCH), 256, sizeof(AttnSmem)>>>(Out);
}

// round 4
// speedup vs baseline: 2.6182x; 2.6182x over previous
#include <cuda_runtime.h>
#include <cuda_bf16.h>
#include <cstdint>
#include <math.h>

// Problem constants
#define DMODEL 1024
#define NBATCH 8
#define SEQ    2048
#define NTOK   (NBATCH * SEQ)   // 16384

// split-bf16 global scratch
__device__ __nv_bfloat16 g_Xhi[NTOK * DMODEL];
__device__ __nv_bfloat16 g_Xlo[NTOK * DMODEL];
__device__ __nv_bfloat16 g_Wthi[3 * DMODEL * DMODEL];  // W^T, [z][n][k]
__device__ __nv_bfloat16 g_Wtlo[3 * DMODEL * DMODEL];
__device__ __nv_bfloat16 g_Qhi[NTOK * DMODEL];
__device__ __nv_bfloat16 g_Qlo[NTOK * DMODEL];
__device__ __nv_bfloat16 g_Khi[NTOK * DMODEL];
__device__ __nv_bfloat16 g_Klo[NTOK * DMODEL];
__device__ __nv_bfloat16 g_Vhi[NTOK * DMODEL];
__device__ __nv_bfloat16 g_Vlo[NTOK * DMODEL];

// ===========================================================================
// helpers
// ===========================================================================
__device__ __forceinline__ uint32_t smem_to_u32(const void* p) {
    uint32_t a;
    asm("{ .reg .u64 t; cvta.to.shared.u64 t, %1; cvt.u32.u64 %0, t; }" : "=r"(a) : "l"(p));
    return a;
}
__device__ __forceinline__ void cpa16(uint32_t d, const void* s) {
    asm volatile("cp.async.cg.shared.global [%0], [%1], 16;" :: "r"(d), "l"(s));
}
#define CP_COMMIT() asm volatile("cp.async.commit_group;")
#define CP_WAIT(N)  asm volatile("cp.async.wait_group %0;" :: "n"(N))

__device__ __forceinline__ void ldsm_x4(uint32_t r[4], uint32_t a) {
    asm volatile("ldmatrix.sync.aligned.m8n8.x4.shared.b16 {%0,%1,%2,%3}, [%4];"
        : "=r"(r[0]), "=r"(r[1]), "=r"(r[2]), "=r"(r[3]) : "r"(a));
}
__device__ __forceinline__ void ldsm_x2(uint32_t r[2], uint32_t a) {
    asm volatile("ldmatrix.sync.aligned.m8n8.x2.shared.b16 {%0,%1}, [%2];"
        : "=r"(r[0]), "=r"(r[1]) : "r"(a));
}
__device__ __forceinline__ void ldsm_x2t(uint32_t r[2], uint32_t a) {
    asm volatile("ldmatrix.sync.aligned.m8n8.x2.trans.shared.b16 {%0,%1}, [%2];"
        : "=r"(r[0]), "=r"(r[1]) : "r"(a));
}
__device__ __forceinline__ void mma_bf16(float c[4], const uint32_t a[4], const uint32_t b[2]) {
    asm volatile("mma.sync.aligned.m16n8k16.row.col.f32.bf16.bf16.f32 "
        "{%0,%1,%2,%3}, {%4,%5,%6,%7}, {%8,%9}, {%0,%1,%2,%3};"
        : "+f"(c[0]), "+f"(c[1]), "+f"(c[2]), "+f"(c[3])
        : "r"(a[0]), "r"(a[1]), "r"(a[2]), "r"(a[3]), "r"(b[0]), "r"(b[1]));
}

// QK-style tile geometry: 128 rows x 64 bf16 cols, padded to 72 elem (144 B)
#define ATILE 18432
#define ABUF  73728    // 4 tiles (Ahi, Alo, Bhi, Blo)

// Load one stage: 4 tiles of [128 x 64] bf16 from row-major [*, DMODEL] sources.
__device__ __forceinline__ void load_stage4(
    uint32_t sb, uint32_t bufo, int tid,
    const __nv_bfloat16* A0, const __nv_bfloat16* A1,
    const __nv_bfloat16* B0, const __nv_bfloat16* B1,
    int arow0, int brow0, int dk)
{
    #pragma unroll
    for (int i = 0; i < 4; i++) {
        const int idx = i * 256 + tid;
        const int row = idx >> 3;
        const int c   = idx & 7;
        const uint32_t so = sb + bufo + row * 144 + c * 16;
        const size_t ga = (size_t)(arow0 + row) * DMODEL + dk + c * 8;
        const size_t gb = (size_t)(brow0 + row) * DMODEL + dk + c * 8;
        cpa16(so,             A0 + ga);
        cpa16(so + ATILE,     A1 + ga);
        cpa16(so + 2 * ATILE, B0 + gb);
        cpa16(so + 3 * ATILE, B1 + gb);
    }
    CP_COMMIT();
}

// One K=64 compute stage (4 k16 steps) of C += A*B with 3-term split.
__device__ __forceinline__ void mma_stage(
    float C[4][4][4], uint32_t sb, uint32_t bufo, int l, int wy, int wx)
{
    #pragma unroll
    for (int kk = 0; kk < 4; kk++) {
        uint32_t ah[4][4], al[4][4];
        #pragma unroll
        for (int mi = 0; mi < 4; mi++) {
            const uint32_t ra = sb + bufo
                + (uint32_t)(wy * 64 + mi * 16 + (l & 15)) * 144
                + (uint32_t)(kk * 16 + ((l >> 4) << 3)) * 2;
            ldsm_x4(ah[mi], ra);
            ldsm_x4(al[mi], ra + ATILE);
        }
        #pragma unroll
        for (int ni = 0; ni < 4; ni++) {
            const uint32_t rb = sb + bufo + 2 * ATILE
                + (uint32_t)(wx * 32 + ni * 8 + (l & 7)) * 144
                + (uint32_t)(kk * 16 + (((l >> 3) & 1) << 3)) * 2;
            uint32_t bh[2], bl[2];
            ldsm_x2(bh, rb);
            ldsm_x2(bl, rb + ATILE);
            #pragma unroll
            for (int mi = 0; mi < 4; mi++) {
                mma_bf16(C[mi][ni], ah[mi], bh);
                mma_bf16(C[mi][ni], ah[mi], bl);
                mma_bf16(C[mi][ni], al[mi], bh);
            }
        }
    }
}

// ===========================================================================
// Convert kernels
// ===========================================================================
__global__ __launch_bounds__(256) void split_x_kernel(const float* __restrict__ X) {
    const int i = blockIdx.x * 256 + threadIdx.x;   // over float4s
    float4 v = ((const float4*)X)[i];
    __nv_bfloat16 h0 = __float2bfloat16(v.x);
    __nv_bfloat16 h1 = __float2bfloat16(v.y);
    __nv_bfloat16 h2 = __float2bfloat16(v.z);
    __nv_bfloat16 h3 = __float2bfloat16(v.w);
    __nv_bfloat16 l0 = __float2bfloat16(v.x - __bfloat162float(h0));
    __nv_bfloat16 l1 = __float2bfloat16(v.y - __bfloat162float(h1));
    __nv_bfloat16 l2 = __float2bfloat16(v.z - __bfloat162float(h2));
    __nv_bfloat16 l3 = __float2bfloat16(v.w - __bfloat162float(h3));
    ((__nv_bfloat162*)g_Xhi)[i * 2 + 0] = __nv_bfloat162(h0, h1);
    ((__nv_bfloat162*)g_Xhi)[i * 2 + 1] = __nv_bfloat162(h2, h3);
    ((__nv_bfloat162*)g_Xlo)[i * 2 + 0] = __nv_bfloat162(l0, l1);
    ((__nv_bfloat162*)g_Xlo)[i * 2 + 1] = __nv_bfloat162(l2, l3);
}

__global__ void splitT_w_kernel(const float* __restrict__ Wq,
                                const float* __restrict__ Wk,
                                const float* __restrict__ Wv) {
    __shared__ float t[32][33];
    const int z = blockIdx.z;
    const float* W = (z == 0) ? Wq : (z == 1) ? Wk : Wv;
    const int k = blockIdx.y * 32 + threadIdx.y;
    const int n = blockIdx.x * 32 + threadIdx.x;
    t[threadIdx.y][threadIdx.x] = W[k * DMODEL + n];
    __syncthreads();
    const int on = blockIdx.x * 32 + threadIdx.y;   // output row (n)
    const int ok = blockIdx.y * 32 + threadIdx.x;   // output col (k)
    float v = t[threadIdx.x][threadIdx.y];
    __nv_bfloat16 h = __float2bfloat16(v);
    __nv_bfloat16 l = __float2bfloat16(v - __bfloat162float(h));
    g_Wthi[(size_t)z * DMODEL * DMODEL + on * DMODEL + ok] = h;
    g_Wtlo[(size_t)z * DMODEL * DMODEL + on * DMODEL + ok] = l;
}

// ===========================================================================
// QKV projection: out = X @ W + b, written as hi/lo bf16 pairs.
// grid (8, 128, 3), 256 threads, warp grid 2x4 (wy m64, wx n32).
// ===========================================================================
#define PROJ_SMEM (2 * ABUF)

__global__ __launch_bounds__(256) void qkv_mma_kernel(
    const float* __restrict__ bq, const float* __restrict__ bk,
    const float* __restrict__ bv)
{
    extern __shared__ char smc[];
    const uint32_t sb = smem_to_u32(smc);
    const int tid = threadIdx.x;
    const int l = tid & 31, w = tid >> 5;
    const int wy = w >> 2, wx = w & 3;
    const int z = blockIdx.z, m0 = blockIdx.y * 128, n0 = blockIdx.x * 128;

    const __nv_bfloat16* Bh = g_Wthi + (size_t)z * DMODEL * DMODEL;
    const __nv_bfloat16* Bl = g_Wtlo + (size_t)z * DMODEL * DMODEL;
    const float* bias = (z == 0) ? bq : (z == 1) ? bk : bv;
    __nv_bfloat16* ohi = (z == 0) ? g_Qhi : (z == 1) ? g_Khi : g_Vhi;
    __nv_bfloat16* olo = (z == 0) ? g_Qlo : (z == 1) ? g_Klo : g_Vlo;

    float C[4][4][4];
    #pragma unroll
    for (int mi = 0; mi < 4; mi++)
        #pragma unroll
        for (int ni = 0; ni < 4; ni++)
            #pragma unroll
            for (int q = 0; q < 4; q++) C[mi][ni][q] = 0.f;

    load_stage4(sb, 0, tid, g_Xhi, g_Xlo, Bh, Bl, m0, n0, 0);
    for (int kc = 0; kc < 16; kc++) {
        if (kc + 1 < 16) {
            load_stage4(sb, ((kc + 1) & 1) * ABUF, tid, g_Xhi, g_Xlo, Bh, Bl,
                        m0, n0, (kc + 1) * 64);
            CP_WAIT(1);
        } else {
            CP_WAIT(0);
        }
        __syncthreads();
        mma_stage(C, sb, (kc & 1) * ABUF, l, wy, wx);
        __syncthreads();
    }

    // epilogue: bias add + hi/lo split store
    #pragma unroll
    for (int mi = 0; mi < 4; mi++)
        #pragma unroll
        for (int ni = 0; ni < 4; ni++)
            #pragma unroll
            for (int h = 0; h < 2; h++) {
                const int r = m0 + wy * 64 + mi * 16 + h * 8 + (l >> 2);
                const int c = n0 + wx * 32 + ni * 8 + 2 * (l & 3);
                const float v0 = C[mi][ni][2 * h + 0] + bias[c];
                const float v1 = C[mi][ni][2 * h + 1] + bias[c + 1];
                const __nv_bfloat16 h0 = __float2bfloat16(v0);
                const __nv_bfloat16 h1 = __float2bfloat16(v1);
                const __nv_bfloat16 l0 = __float2bfloat16(v0 - __bfloat162float(h0));
                const __nv_bfloat16 l1 = __float2bfloat16(v1 - __bfloat162float(h1));
                *(__nv_bfloat162*)&ohi[(size_t)r * DMODEL + c] = __nv_bfloat162(h0, h1);
                *(__nv_bfloat162*)&olo[(size_t)r * DMODEL + c] = __nv_bfloat162(l0, l1);
            }
}

// ===========================================================================
// Attention: flash-style with mma.sync for S and PV.
// grid (16, 8), 256 threads, warp grid 2x4.
// ===========================================================================
#define PTILEB   34816          // 128 x 136 bf16 (272 B rows)
#define VBUF     69632          // Vhi + Vlo, one stage
#define OFF_P    147456
#define OFF_PLO  (OFF_P + PTILEB)
#define OFF_PMAX (OFF_P + 2 * PTILEB)        // 217088: float[4][128]
#define OFF_PSUM (OFF_PMAX + 2048)           // 219136: float[4][128]
#define OFF_MS   (OFF_PSUM + 2048)           // 221184: float[128]
#define OFF_LS   (OFF_MS + 512)              // 221696: float[128]
#define ATTN_SMEM 222208

__global__ __launch_bounds__(256) void attn_mma_kernel(float* __restrict__ Out)
{
    extern __shared__ char smc[];
    const uint32_t sb = smem_to_u32(smc);
    float* pmax = (float*)(smc + OFF_PMAX);
    float* psum = (float*)(smc + OFF_PSUM);
    float* m_s  = (float*)(smc + OFF_MS);
    float* l_s  = (float*)(smc + OFF_LS);

    const int tid = threadIdx.x;
    const int l = tid & 31, w = tid >> 5;
    const int wy = w >> 2, wx = w & 3;
    const int b = blockIdx.y, qt = blockIdx.x;
    const int q0 = b * SEQ + qt * 128;
    const int kb = b * SEQ;

    if (tid < 128) {
        m_s[tid] = __int_as_float(0xff800000);
        l_s[tid] = 0.f;
    }
    __syncthreads();

    for (int kt = 0; kt < 16; kt++) {
        const int k0 = kb + kt * 128;

        // ================= S = Q K^T (split-bf16 mma) =================
        float C[4][4][4];
        #pragma unroll
        for (int mi = 0; mi < 4; mi++)
            #pragma unroll
            for (int ni = 0; ni < 4; ni++)
                #pragma unroll
                for (int q = 0; q < 4; q++) C[mi][ni][q] = 0.f;

        load_stage4(sb, 0, tid, g_Qhi, g_Qlo, g_Khi, g_Klo, q0, k0, 0);
        for (int s = 0; s < 16; s++) {
            if (s + 1 < 16) {
                load_stage4(sb, ((s + 1) & 1) * ABUF, tid, g_Qhi, g_Qlo,
                            g_Khi, g_Klo, q0, k0, (s + 1) * 64);
                CP_WAIT(1);
            } else {
                CP_WAIT(0);
            }
            __syncthreads();
            mma_stage(C, sb, (s & 1) * ABUF, l, wy, wx);
            __syncthreads();
        }

        // prefetch V chunk 0 (slot 0 does not overlap S buffer 1 just used)
        {
            #pragma unroll
            for (int i = 0; i < 8; i++) {
                const int idx = i * 256 + tid;
                const int row = idx >> 4, c = idx & 15;
                const uint32_t dst = sb + (uint32_t)(row * 272 + c * 16);
                const size_t g = (size_t)(k0 + row) * DMODEL + c * 8;
                cpa16(dst, g_Vhi + g);
                cpa16(dst + PTILEB, g_Vlo + g);
            }
            CP_COMMIT();
        }

        // ================= online softmax =================
        float rmax[8];
        #pragma unroll
        for (int mi = 0; mi < 4; mi++)
            #pragma unroll
            for (int h = 0; h < 2; h++) {
                float m = __int_as_float(0xff800000);
                #pragma unroll
                for (int ni = 0; ni < 4; ni++)
                    m = fmaxf(m, fmaxf(C[mi][ni][2 * h], C[mi][ni][2 * h + 1]));
                m = fmaxf(m, __shfl_xor_sync(0xffffffffu, m, 1));
                m = fmaxf(m, __shfl_xor_sync(0xffffffffu, m, 2));
                rmax[mi * 2 + h] = m;
                if ((l & 3) == 0)
                    pmax[wx * 128 + wy * 64 + mi * 16 + h * 8 + (l >> 2)] = m;
            }
        __syncthreads();

        float alpha[8], mnew[8];
        #pragma unroll
        for (int mi = 0; mi < 4; mi++)
            #pragma unroll
            for (int h = 0; h < 2; h++) {
                const int sl = mi * 2 + h;
                const int row = wy * 64 + mi * 16 + h * 8 + (l >> 2);
                const float mo = m_s[row];
                float mx = fmaxf(fmaxf(pmax[row], pmax[128 + row]),
                                 fmaxf(pmax[256 + row], pmax[384 + row]));
                const float mn = fmaxf(mo, mx);
                mnew[sl] = mn;
                alpha[sl] = __expf(mo - mn);
                float ssum = 0.f;
                #pragma unroll
                for (int ni = 0; ni < 4; ni++) {
                    float e0 = __expf(C[mi][ni][2 * h] - mn);
                    float e1 = __expf(C[mi][ni][2 * h + 1] - mn);
                    C[mi][ni][2 * h] = e0;
                    C[mi][ni][2 * h + 1] = e1;
                    ssum += e0 + e1;
                    // store P hi/lo pair to smem
                    const int col = wx * 32 + ni * 8 + 2 * (l & 3);
                    const __nv_bfloat16 p0h = __float2bfloat16(e0);
                    const __nv_bfloat16 p1h = __float2bfloat16(e1);
                    const __nv_bfloat16 p0l = __float2bfloat16(e0 - __bfloat162float(p0h));
                    const __nv_bfloat16 p1l = __float2bfloat16(e1 - __bfloat162float(p1h));
                    *(__nv_bfloat162*)(smc + OFF_P   + row * 272 + col * 2) = __nv_bfloat162(p0h, p1h);
                    *(__nv_bfloat162*)(smc + OFF_PLO + row * 272 + col * 2) = __nv_bfloat162(p0l, p1l);
                }
                ssum += __shfl_xor_sync(0xffffffffu, ssum, 1);
                ssum += __shfl_xor_sync(0xffffffffu, ssum, 2);
                if ((l & 3) == 0) psum[wx * 128 + row] = ssum;
            }
        __syncthreads();

        if (wx == 0 && (l & 3) == 0) {
            #pragma unroll
            for (int mi = 0; mi < 4; mi++)
                #pragma unroll
                for (int h = 0; h < 2; h++) {
                    const int sl = mi * 2 + h;
                    const int row = wy * 64 + mi * 16 + h * 8 + (l >> 2);
                    const float ss = psum[row] + psum[128 + row] +
                                     psum[256 + row] + psum[384 + row];
                    l_s[row] = l_s[row] * alpha[sl] + ss;
                    m_s[row] = mnew[sl];
                }
        }
        __syncthreads();

        // ================= O += P V (split-bf16 mma) =================
        const bool first = (kt == 0);
        const bool last  = (kt == 15);

        for (int nc = 0; nc < 8; nc++) {
            if (nc + 1 < 8) {
                const uint32_t slot = ((nc + 1) & 1) * VBUF;
                #pragma unroll
                for (int i = 0; i < 8; i++) {
                    const int idx = i * 256 + tid;
                    const int row = idx >> 4, c = idx & 15;
                    const uint32_t dst = sb + slot + (uint32_t)(row * 272 + c * 16);
                    const size_t g = (size_t)(k0 + row) * DMODEL + (nc + 1) * 128 + c * 8;
                    cpa16(dst, g_Vhi + g);
                    cpa16(dst + PTILEB, g_Vlo + g);
                }
                CP_COMMIT();
                CP_WAIT(1);
            } else {
                CP_WAIT(0);
            }
            __syncthreads();

            float Oc[4][4][4];
            if (first) {
                #pragma unroll
                for (int mi = 0; mi < 4; mi++)
                    #pragma unroll
                    for (int ni = 0; ni < 4; ni++)
                        #pragma unroll
                        for (int q = 0; q < 4; q++) Oc[mi][ni][q] = 0.f;
            } else {
                #pragma unroll
                for (int mi = 0; mi < 4; mi++)
                    #pragma unroll
                    for (int ni = 0; ni < 4; ni++)
                        #pragma unroll
                        for (int h = 0; h < 2; h++) {
                            const int r = wy * 64 + mi * 16 + h * 8 + (l >> 2);
                            const int c = nc * 128 + wx * 32 + ni * 8 + 2 * (l & 3);
                            const float2 p = *(const float2*)&Out[(size_t)(q0 + r) * DMODEL + c];
                            Oc[mi][ni][2 * h]     = p.x * alpha[mi * 2 + h];
                            Oc[mi][ni][2 * h + 1] = p.y * alpha[mi * 2 + h];
                        }
            }

            const uint32_t slot = (nc & 1) * VBUF;
            #pragma unroll
            for (int kk = 0; kk < 8; kk++) {
                uint32_t ph[4][4], pl[4][4];
                #pragma unroll
                for (int mi = 0; mi < 4; mi++) {
                    const uint32_t ra = sb + OFF_P
                        + (uint32_t)(wy * 64 + mi * 16 + (l & 15)) * 272
                        + (uint32_t)(kk * 16 + ((l >> 4) << 3)) * 2;
                    ldsm_x4(ph[mi], ra);
                    ldsm_x4(pl[mi], ra + PTILEB);
                }
                #pragma unroll
                for (int ni = 0; ni < 4; ni++) {
                    const uint32_t rb = sb + slot
                        + (uint32_t)(kk * 16 + (l & 15)) * 272
                        + (uint32_t)(wx * 32 + ni * 8) * 2;
                    uint32_t vh[2], vl[2];
                    ldsm_x2t(vh, rb);
                    ldsm_x2t(vl, rb + PTILEB);
                    #pragma unroll
                    for (int mi = 0; mi < 4; mi++) {
                        mma_bf16(Oc[mi][ni], ph[mi], vh);
                        mma_bf16(Oc[mi][ni], ph[mi], vl);
                        mma_bf16(Oc[mi][ni], pl[mi], vh);
                    }
                }
            }

            // store O chunk
            #pragma unroll
            for (int mi = 0; mi < 4; mi++)
                #pragma unroll
                for (int ni = 0; ni < 4; ni++)
                    #pragma unroll
                    for (int h = 0; h < 2; h++) {
                        const int r = wy * 64 + mi * 16 + h * 8 + (l >> 2);
                        const int c = nc * 128 + wx * 32 + ni * 8 + 2 * (l & 3);
                        const float sc = last ? (1.f / l_s[r]) : 1.f;
                        float2 p;
                        p.x = Oc[mi][ni][2 * h] * sc;
                        p.y = Oc[mi][ni][2 * h + 1] * sc;
                        *(float2*)&Out[(size_t)(q0 + r) * DMODEL + c] = p;
                    }
            __syncthreads();
        }
    }
}

// ---------------------------------------------------------------------------
extern "C" void kernel_launch(void* const* d_in, const int* in_sizes, int n_in,
                              void* d_out, int out_size)
{
    const float* X  = (const float*)d_in[0];
    const float* Wq = (const float*)d_in[1];
    const float* bq = (const float*)d_in[2];
    const float* Wk = (const float*)d_in[3];
    const float* bk = (const float*)d_in[4];
    const float* Wv = (const float*)d_in[5];
    const float* bv = (const float*)d_in[6];
    float* Out = (float*)d_out;

    split_x_kernel<<<NTOK * DMODEL / 4 / 256, 256>>>(X);
    splitT_w_kernel<<<dim3(32, 32, 3), dim3(32, 32)>>>(Wq, Wk, Wv);

    cudaFuncSetAttribute(qkv_mma_kernel, cudaFuncAttributeMaxDynamicSharedMemorySize, PROJ_SMEM);
    qkv_mma_kernel<<<dim3(DMODEL / 128, NTOK / 128, 3), 256, PROJ_SMEM>>>(bq, bk, bv);

    cudaFuncSetAttribute(attn_mma_kernel, cudaFuncAttributeMaxDynamicSharedMemorySize, ATTN_SMEM);
    attn_mma_kernel<<<dim3(SEQ / 128, NBATCH), 256, ATTN_SMEM>>>(Out);
}